// round 13
// baseline (speedup 1.0000x reference)
#include <cuda_runtime.h>
#include <cmath>

#define Tn 2048
#define Dm 256
#define BRn 4
#define Bqn 2
#define KSEL 15
#define SCALE_ACT 1.8137993642342178f

// ---------------- scratch (device globals; no allocation) ----------------
__device__ float g_inv[128];
__device__ float g_cos[Tn * 128];
__device__ float g_sin[Tn * 128];
__device__ float g_I[Bqn * Tn * BRn * Dm];     // (b, t, r*256+d) rows of 1024
__device__ float g_P[Bqn * Tn * Dm];           // (b, t, d)
__device__ float g_Pn[Bqn * Tn * Dm];          // normalized P rows
__device__ float g_logits[Bqn * BRn * Tn * Tn];// (b*4+r, t, s) 134MB
__device__ int   g_topk[Bqn * BRn * Tn * KSEL];
__device__ float g_V[Bqn * Tn * BRn * Dm];     // (b, t, r*256+d)
__device__ float g_palT[16 * 16 * Dm];         // (y, x, d) transposed palette
__device__ float g_sk[4 * 4096 * 256];         // split-K partials (16MB)

// ---------------- inv frequencies: the ONLY fp64 left ----------------
__global__ void k_inv() {
    int i = threadIdx.x;            // 0..127
    float e = (float)(2 * i) * (1.0f / 256.0f);
    float pw = (float)pow(10000.0, (double)e);
    g_inv[i] = 1.0f / pw;
}

// ---------------- RoPE tables (pure fp32, sincosf <= 2ulp) ----------------
__global__ void k_rope_tables() {
    int t = blockIdx.x;
    int i = threadIdx.x;            // 0..127
    float f = (float)t * g_inv[i];  // f32 outer product, matches numpy
    float s, c;
    sincosf(f, &s, &c);
    g_cos[t * 128 + i] = c;
    g_sin[t * 128 + i] = s;
}

// ---------------- palette transpose (d,y,x) -> (y,x,d) ----------------
__global__ void k_palT(const float* __restrict__ pal) {
    int d = blockIdx.x;             // 0..255
    int p = threadIdx.x;            // 0..255 = y*16+x
    g_palT[p * 256 + d] = pal[d * 256 + p];
}

// ---------------- 64x64 GEMM (sequential-k; used for P: selection-critical) --
__global__ __launch_bounds__(256) void k_gemm_rr(
    const float* __restrict__ A, const float* __restrict__ B, float* __restrict__ C,
    int K, int lda, int ldb, int ldc, float alpha)
{
    __shared__ float As[64][17];
    __shared__ float Bs[64][17];
    int tid = threadIdx.x;
    int m0 = blockIdx.y * 64, n0 = blockIdx.x * 64;
    int tx = tid & 15, ty = tid >> 4;
    float acc[4][4];
#pragma unroll
    for (int i = 0; i < 4; i++)
#pragma unroll
        for (int j = 0; j < 4; j++) acc[i][j] = 0.f;

    int alr = tid >> 2, alc = (tid & 3) << 2;
    int bkk = tid >> 4, bnn = (tid & 15) << 2;

    for (int k0 = 0; k0 < K; k0 += 16) {
        float4 av = *(const float4*)&A[(size_t)(m0 + alr) * lda + k0 + alc];
        As[alr][alc] = av.x; As[alr][alc + 1] = av.y;
        As[alr][alc + 2] = av.z; As[alr][alc + 3] = av.w;
        float4 bv = *(const float4*)&B[(size_t)(k0 + bkk) * ldb + n0 + bnn];
        Bs[bnn][bkk] = bv.x; Bs[bnn + 1][bkk] = bv.y;
        Bs[bnn + 2][bkk] = bv.z; Bs[bnn + 3][bkk] = bv.w;
        __syncthreads();
#pragma unroll
        for (int kk = 0; kk < 16; kk++) {
            float a[4], bb[4];
#pragma unroll
            for (int i = 0; i < 4; i++) a[i] = As[ty + 16 * i][kk];
#pragma unroll
            for (int j = 0; j < 4; j++) bb[j] = Bs[tx + 16 * j][kk];
#pragma unroll
            for (int i = 0; i < 4; i++)
#pragma unroll
                for (int j = 0; j < 4; j++) acc[i][j] += a[i] * bb[j];
        }
        __syncthreads();
    }
#pragma unroll
    for (int i = 0; i < 4; i++)
#pragma unroll
        for (int j = 0; j < 4; j++)
            C[(size_t)(m0 + ty + 16 * i) * ldc + n0 + tx + 16 * j] = acc[i][j] * alpha;
}

// ---------------- 128x128 / 8x8 GEMM, C = alpha * A(MxK) @ B(KxN) ----
__global__ __launch_bounds__(256, 2) void k_gemm128(
    const float* __restrict__ A, const float* __restrict__ B, float* __restrict__ C,
    int K, int lda, int ldb, int ldc, float alpha)
{
    __shared__ float As[16][132];
    __shared__ float Bs[16][132];
    int tid = threadIdx.x;
    int tx = tid & 15, ty = tid >> 4;
    int m0 = blockIdx.y * 128, n0 = blockIdx.x * 128;

    int ar = tid >> 2, ac = (tid & 3) << 2;
    int br = tid >> 4, bc = (tid & 15) << 2;

    const float* Ap0 = A + (size_t)(m0 + ar) * lda + ac;
    const float* Ap1 = Ap0 + (size_t)64 * lda;
    const float* Bq  = B + (size_t)br * ldb + n0 + bc;

    float4 a0 = *(const float4*)Ap0;
    float4 a1 = *(const float4*)Ap1;
    float4 b0 = *(const float4*)Bq;
    float4 b1 = *(const float4*)(Bq + 64);

    float acc[8][8];
#pragma unroll
    for (int i = 0; i < 8; i++)
#pragma unroll
        for (int j = 0; j < 8; j++) acc[i][j] = 0.f;

    int nk = K >> 4;
    for (int kt = 0; kt < nk; kt++) {
        As[ac + 0][ar] = a0.x; As[ac + 1][ar] = a0.y;
        As[ac + 2][ar] = a0.z; As[ac + 3][ar] = a0.w;
        As[ac + 0][ar + 64] = a1.x; As[ac + 1][ar + 64] = a1.y;
        As[ac + 2][ar + 64] = a1.z; As[ac + 3][ar + 64] = a1.w;
        *(float4*)&Bs[br][bc]      = b0;
        *(float4*)&Bs[br][bc + 64] = b1;
        __syncthreads();
        if (kt + 1 < nk) {
            Ap0 += 16; Ap1 += 16; Bq += (size_t)16 * ldb;
            a0 = *(const float4*)Ap0;
            a1 = *(const float4*)Ap1;
            b0 = *(const float4*)Bq;
            b1 = *(const float4*)(Bq + 64);
        }
#pragma unroll
        for (int kk = 0; kk < 16; kk++) {
            float4 x0 = *(float4*)&As[kk][ty * 8];
            float4 x1 = *(float4*)&As[kk][ty * 8 + 4];
            float4 y0 = *(float4*)&Bs[kk][tx * 8];
            float4 y1 = *(float4*)&Bs[kk][tx * 8 + 4];
            float a[8] = {x0.x, x0.y, x0.z, x0.w, x1.x, x1.y, x1.z, x1.w};
            float bb[8] = {y0.x, y0.y, y0.z, y0.w, y1.x, y1.y, y1.z, y1.w};
#pragma unroll
            for (int i = 0; i < 8; i++)
#pragma unroll
                for (int j = 0; j < 8; j++) acc[i][j] += a[i] * bb[j];
        }
        __syncthreads();
    }
#pragma unroll
    for (int i = 0; i < 8; i++) {
        float* crow = C + (size_t)(m0 + ty * 8 + i) * ldc + n0 + tx * 8;
        float4 o0 = make_float4(acc[i][0] * alpha, acc[i][1] * alpha,
                                acc[i][2] * alpha, acc[i][3] * alpha);
        float4 o1 = make_float4(acc[i][4] * alpha, acc[i][5] * alpha,
                                acc[i][6] * alpha, acc[i][7] * alpha);
        *(float4*)crow = o0;
        *(float4*)(crow + 4) = o1;
    }
}

// ---------------- split-K variant (POST-SELECTION USE ONLY: out GEMM) -----
__global__ __launch_bounds__(256, 2) void k_gemm128sk(
    const float* __restrict__ A, const float* __restrict__ B,
    int Kper, int lda, int ldb, int N)
{
    int z = blockIdx.z;
    A += (size_t)z * Kper;                 // k-offset in A columns
    B += (size_t)z * Kper * ldb;           // k-offset in B rows
    float* C = g_sk + (size_t)z * 4096 * 256;

    __shared__ float As[16][132];
    __shared__ float Bs[16][132];
    int tid = threadIdx.x;
    int tx = tid & 15, ty = tid >> 4;
    int m0 = blockIdx.y * 128, n0 = blockIdx.x * 128;

    int ar = tid >> 2, ac = (tid & 3) << 2;
    int br = tid >> 4, bc = (tid & 15) << 2;

    const float* Ap0 = A + (size_t)(m0 + ar) * lda + ac;
    const float* Ap1 = Ap0 + (size_t)64 * lda;
    const float* Bq  = B + (size_t)br * ldb + n0 + bc;

    float4 a0 = *(const float4*)Ap0;
    float4 a1 = *(const float4*)Ap1;
    float4 b0 = *(const float4*)Bq;
    float4 b1 = *(const float4*)(Bq + 64);

    float acc[8][8];
#pragma unroll
    for (int i = 0; i < 8; i++)
#pragma unroll
        for (int j = 0; j < 8; j++) acc[i][j] = 0.f;

    int nk = Kper >> 4;
    for (int kt = 0; kt < nk; kt++) {
        As[ac + 0][ar] = a0.x; As[ac + 1][ar] = a0.y;
        As[ac + 2][ar] = a0.z; As[ac + 3][ar] = a0.w;
        As[ac + 0][ar + 64] = a1.x; As[ac + 1][ar + 64] = a1.y;
        As[ac + 2][ar + 64] = a1.z; As[ac + 3][ar + 64] = a1.w;
        *(float4*)&Bs[br][bc]      = b0;
        *(float4*)&Bs[br][bc + 64] = b1;
        __syncthreads();
        if (kt + 1 < nk) {
            Ap0 += 16; Ap1 += 16; Bq += (size_t)16 * ldb;
            a0 = *(const float4*)Ap0;
            a1 = *(const float4*)Ap1;
            b0 = *(const float4*)Bq;
            b1 = *(const float4*)(Bq + 64);
        }
#pragma unroll
        for (int kk = 0; kk < 16; kk++) {
            float4 x0 = *(float4*)&As[kk][ty * 8];
            float4 x1 = *(float4*)&As[kk][ty * 8 + 4];
            float4 y0 = *(float4*)&Bs[kk][tx * 8];
            float4 y1 = *(float4*)&Bs[kk][tx * 8 + 4];
            float a[8] = {x0.x, x0.y, x0.z, x0.w, x1.x, x1.y, x1.z, x1.w};
            float bb[8] = {y0.x, y0.y, y0.z, y0.w, y1.x, y1.y, y1.z, y1.w};
#pragma unroll
            for (int i = 0; i < 8; i++)
#pragma unroll
                for (int j = 0; j < 8; j++) acc[i][j] += a[i] * bb[j];
        }
        __syncthreads();
    }
#pragma unroll
    for (int i = 0; i < 8; i++) {
        float* crow = C + (size_t)(m0 + ty * 8 + i) * N + n0 + tx * 8;
        *(float4*)crow       = *(float4*)&acc[i][0];
        *(float4*)(crow + 4) = *(float4*)&acc[i][4];
    }
}

// ---------------- sum 4 split-K slabs: dst = alpha * sum ----------------
__global__ void k_sumK(float* __restrict__ dst, float alpha, int n4) {
    int i = blockIdx.x * 256 + threadIdx.x;
    if (i >= n4) return;
    const float4* s = (const float4*)g_sk;
    int n = n4;
    float4 v0 = s[i], v1 = s[i + n], v2 = s[i + 2 * n], v3 = s[i + 3 * n];
    float4 o;
    o.x = alpha * (v0.x + v1.x + v2.x + v3.x);
    o.y = alpha * (v0.y + v1.y + v2.y + v3.y);
    o.z = alpha * (v0.z + v1.z + v2.z + v3.z);
    o.w = alpha * (v0.w + v1.w + v2.w + v3.w);
    ((float4*)dst)[i] = o;
}

// ---------------- RoPE on I (elementwise, pairs) ----------------
__global__ void k_rope_I() {
    int p = blockIdx.x * 256 + threadIdx.x;
    int i = p & 127;
    int row = p >> 7;
    int t = (row >> 2) & (Tn - 1);
    float c = g_cos[t * 128 + i], s = g_sin[t * 128 + i];
    float2* ptr = (float2*)g_I;
    size_t o2 = (size_t)(row >> 2) * 512 + (size_t)(row & 3) * 128 + i;
    float2 v = ptr[o2];
    float y1 = v.x * c - v.y * s;
    float y2 = v.x * s + v.y * c;
    ptr[o2] = make_float2(y1, y2);
}

// ---------------- RoPE on P + write normalized Pn ----------------
__global__ void k_rope_P() {
    int row = blockIdx.x;           // b*Tn + t
    int t = row & (Tn - 1);
    int i = threadIdx.x;            // 0..127
    float c = g_cos[t * 128 + i], s = g_sin[t * 128 + i];
    float2* P2 = (float2*)g_P;
    float2* Pn2 = (float2*)g_Pn;
    float2 v = P2[(size_t)row * 128 + i];
    float y1 = v.x * c - v.y * s;
    float y2 = v.x * s + v.y * c;
    float ss = y1 * y1 + y2 * y2;
#pragma unroll
    for (int o = 16; o; o >>= 1) ss += __shfl_xor_sync(0xffffffffu, ss, o);
    __shared__ float sr[4];
    if ((i & 31) == 0) sr[i >> 5] = ss;
    __syncthreads();
    float tot = sr[0] + sr[1] + sr[2] + sr[3];
    float inv = 1.f / fmaxf(sqrtf(tot), 1e-12f);
    P2[(size_t)row * 128 + i] = make_float2(y1, y2);
    Pn2[(size_t)row * 128 + i] = make_float2(y1 * inv, y2 * inv);
}

// ---------------- causal logits: 128x128 tile, 8x8 microtile --------------
__global__ __launch_bounds__(256, 2) void k_logits128() {
    int sT = blockIdx.x, tT = blockIdx.y;
    if (sT > tT) return;
    int bz = blockIdx.z;                        // b*4 + r
    int b = bz >> 2, r = bz & 3;
    const float* A  = g_I + (size_t)b * Tn * 1024 + r * 256;
    const float* Bp = g_P + (size_t)b * Tn * 256;
    float* C = g_logits + (size_t)bz * Tn * Tn;

    __shared__ float As[16][132];
    __shared__ float Bs[16][132];
    int tid = threadIdx.x;
    int tx = tid & 15, ty = tid >> 4;
    int m0 = tT * 128, n0 = sT * 128;

    int ar = tid >> 2, ac = (tid & 3) << 2;

    const float* Ap0 = A  + (size_t)(m0 + ar) * 1024 + ac;
    const float* Ap1 = Ap0 + (size_t)64 * 1024;
    const float* Bq0 = Bp + (size_t)(n0 + ar) * 256 + ac;
    const float* Bq1 = Bq0 + (size_t)64 * 256;

    float4 a0 = *(const float4*)Ap0;
    float4 a1 = *(const float4*)Ap1;
    float4 b0 = *(const float4*)Bq0;
    float4 b1 = *(const float4*)Bq1;

    float acc[8][8];
#pragma unroll
    for (int i = 0; i < 8; i++)
#pragma unroll
        for (int j = 0; j < 8; j++) acc[i][j] = 0.f;

    for (int kt = 0; kt < 16; kt++) {
        As[ac + 0][ar] = a0.x; As[ac + 1][ar] = a0.y;
        As[ac + 2][ar] = a0.z; As[ac + 3][ar] = a0.w;
        As[ac + 0][ar + 64] = a1.x; As[ac + 1][ar + 64] = a1.y;
        As[ac + 2][ar + 64] = a1.z; As[ac + 3][ar + 64] = a1.w;
        Bs[ac + 0][ar] = b0.x; Bs[ac + 1][ar] = b0.y;
        Bs[ac + 2][ar] = b0.z; Bs[ac + 3][ar] = b0.w;
        Bs[ac + 0][ar + 64] = b1.x; Bs[ac + 1][ar + 64] = b1.y;
        Bs[ac + 2][ar + 64] = b1.z; Bs[ac + 3][ar + 64] = b1.w;
        __syncthreads();
        if (kt < 15) {
            Ap0 += 16; Ap1 += 16; Bq0 += 16; Bq1 += 16;
            a0 = *(const float4*)Ap0;
            a1 = *(const float4*)Ap1;
            b0 = *(const float4*)Bq0;
            b1 = *(const float4*)Bq1;
        }
#pragma unroll
        for (int kk = 0; kk < 16; kk++) {
            float4 x0 = *(float4*)&As[kk][ty * 8];
            float4 x1 = *(float4*)&As[kk][ty * 8 + 4];
            float4 y0 = *(float4*)&Bs[kk][tx * 8];
            float4 y1 = *(float4*)&Bs[kk][tx * 8 + 4];
            float a[8] = {x0.x, x0.y, x0.z, x0.w, x1.x, x1.y, x1.z, x1.w};
            float bb[8] = {y0.x, y0.y, y0.z, y0.w, y1.x, y1.y, y1.z, y1.w};
#pragma unroll
            for (int i = 0; i < 8; i++)
#pragma unroll
                for (int j = 0; j < 8; j++) acc[i][j] += a[i] * bb[j];
        }
        __syncthreads();
    }
#pragma unroll
    for (int i = 0; i < 8; i++) {
        float* crow = C + (size_t)(m0 + ty * 8 + i) * Tn + n0 + tx * 8;
        float4 o0 = make_float4(acc[i][0] * 0.0625f, acc[i][1] * 0.0625f,
                                acc[i][2] * 0.0625f, acc[i][3] * 0.0625f);
        float4 o1 = make_float4(acc[i][4] * 0.0625f, acc[i][5] * 0.0625f,
                                acc[i][6] * 0.0625f, acc[i][7] * 0.0625f);
        *(float4*)crow = o0;
        *(float4*)(crow + 4) = o1;
    }
}

// ---------------- top-15 v2: register sorting-network + head-merge ----------
// Exactly reproduces jax.lax.top_k order: (value desc, index asc) total order.
#define CE(i, j) { \
    bool sw = (v[j] > v[i]) || (v[j] == v[i] && ix[j] < ix[i]); \
    float tv = sw ? v[j] : v[i];  float uv = sw ? v[i] : v[j]; \
    int   ti = sw ? ix[j] : ix[i]; int ui = sw ? ix[i] : ix[j]; \
    v[i] = tv; v[j] = uv; ix[i] = ti; ix[j] = ui; }

__global__ __launch_bounds__(256) void k_topk() {
    __shared__ float svv[2][8];
    __shared__ int   svi[2][8];
    int bid = blockIdx.x;           // br*Tn + t
    int t = bid & (Tn - 1);
    const float* row = g_logits + (size_t)bid * Tn;
    int L = t + 1;                  // causal: only s <= t valid
    int tid = threadIdx.x;
    int lane = tid & 31, wid = tid >> 5;

    // load up to 8 strided elements into registers
    float v[8]; int ix[8];
#pragma unroll
    for (int q = 0; q < 8; q++) {
        int i = tid + 256 * q;
        bool ok = (i < L);
        v[q]  = ok ? row[i] : -INFINITY;
        ix[q] = ok ? i : 0x7fffffff;
    }
    // Batcher odd-even merge sort, 8 elements, 19 CEs (desc value, asc index)
    CE(0,1) CE(2,3) CE(4,5) CE(6,7)
    CE(0,2) CE(1,3) CE(4,6) CE(5,7)
    CE(1,2) CE(5,6)
    CE(0,4) CE(1,5) CE(2,6) CE(3,7)
    CE(2,4) CE(3,5)
    CE(1,2) CE(3,4) CE(5,6)

    for (int it = 0; it < KSEL; it++) {
        float bv = v[0]; int bi = ix[0];
#pragma unroll
        for (int o = 16; o; o >>= 1) {
            float ov = __shfl_down_sync(0xffffffffu, bv, o);
            int   oi = __shfl_down_sync(0xffffffffu, bi, o);
            if (ov > bv || (ov == bv && oi < bi)) { bv = ov; bi = oi; }
        }
        int buf = it & 1;
        if (lane == 0) { svv[buf][wid] = bv; svi[buf][wid] = bi; }
        __syncthreads();
        float fb = svv[buf][0]; int fi = svi[buf][0];
#pragma unroll
        for (int w = 1; w < 8; w++) {
            float wv = svv[buf][w]; int wi = svi[buf][w];
            if (wv > fb || (wv == fb && wi < fi)) { fb = wv; fi = wi; }
        }
        if (tid == 0) g_topk[bid * KSEL + it] = (fi == 0x7fffffff) ? 0 : fi;
        if (ix[0] == fi) {          // unique owner pops its head
#pragma unroll
            for (int q = 0; q < 7; q++) { v[q] = v[q + 1]; ix[q] = ix[q + 1]; }
            v[7] = -INFINITY; ix[7] = 0x7fffffff;
        }
    }
}
#undef CE

// ---------------- constellation v2: register-outer-product gram ----------
__global__ __launch_bounds__(256) void k_constellation(
    const float* __restrict__ W1, const float* __restrict__ b1,
    const float* __restrict__ W2, const float* __restrict__ b2,
    const float* __restrict__ Wc, const float* __restrict__ bc,
    const float* __restrict__ Wm, const float* __restrict__ bm)
{
    __shared__ float sM[16][Dm];       // rows 0..14 = Pn_sel, row 15 = I_n
    __shared__ float sS[16][17];       // full 16x16 gram (incl. I row)
    __shared__ float sRel[KSEL][18];
    __shared__ float sH1[KSEL][64];
    __shared__ float sH2[KSEL][66];
    __shared__ int   sIdx[KSEL];
    __shared__ float sZ[KSEL][2];
    __shared__ float sMix[KSEL];
    __shared__ float sWk[KSEL];
    __shared__ int   sX0[KSEL], sY0[KSEL];
    __shared__ float sWx[KSEL], sWy[KSEL];
    __shared__ float sred[8];

    int tid = threadIdx.x;
    int bid = blockIdx.x;
    int t = bid & (Tn - 1);
    int br = bid >> 11;
    int b = br >> 2;
    int r = br & 3;
    int kept = min(t + 1, KSEL);
    int wid = tid >> 5, lane = tid & 31;

    if (tid < KSEL) sIdx[tid] = (tid < kept) ? g_topk[bid * KSEL + tid] : 0;
    __syncthreads();

    // selected normalized P rows (zeroed beyond kept)
    for (int e = tid; e < KSEL * Dm; e += 256) {
        int k = e >> 8, d = e & 255;
        sM[k][d] = (k < kept) ? g_Pn[(size_t)(b * Tn + sIdx[k]) * Dm + d] : 0.f;
    }
    // normalize I row into sM[15]
    float iv = g_I[(size_t)(b * Tn + t) * 1024 + r * 256 + tid];
    float ss = iv * iv;
#pragma unroll
    for (int o = 16; o; o >>= 1) ss += __shfl_xor_sync(0xffffffffu, ss, o);
    if ((tid & 31) == 0) sred[tid >> 5] = ss;
    __syncthreads();
    float tot = 0.f;
#pragma unroll
    for (int w = 0; w < 8; w++) tot += sred[w];
    float inv = 1.f / fmaxf(sqrtf(tot), 1e-12f);
    sM[15][tid] = iv * inv;
    __syncthreads();

    // ---- gram: warp w computes rows 2w, 2w+1 of S = M M^T (16x16) ----
    {
        int k0 = 2 * wid, k1 = 2 * wid + 1;
        float p0[16], p1[16];
#pragma unroll
        for (int j = 0; j < 16; j++) { p0[j] = 0.f; p1[j] = 0.f; }
#pragma unroll
        for (int q = 0; q < 8; q++) {
            int d = q * 32 + lane;
            float m[16];
#pragma unroll
            for (int i = 0; i < 16; i++) m[i] = sM[i][d];
            float a0 = m[k0 & 15];
            float a1 = m[k1 & 15];
#pragma unroll
            for (int j = 0; j < 16; j++) {
                p0[j] += a0 * m[j];
                p1[j] += a1 * m[j];
            }
        }
#pragma unroll
        for (int j = 0; j < 16; j++) {
            float s0 = p0[j], s1 = p1[j];
#pragma unroll
            for (int o = 16; o; o >>= 1) {
                s0 += __shfl_xor_sync(0xffffffffu, s0, o);
                s1 += __shfl_xor_sync(0xffffffffu, s1, o);
            }
            if (lane == j) { sS[k0][j] = s0; sS[k1][j] = s1; }
        }
    }
    __syncthreads();

    // build rel features (15 x 17)
    if (tid < KSEL * 17) {
        int k = tid / 17, i = tid - k * 17;
        float v;
        if (i < 15)       v = fminf(fmaxf(sS[k][i], -1.f), 1.f);
        else if (i == 15) v = fminf(fmaxf(sS[15][k], -1.f), 1.f);
        else              v = (k < kept) ? (float)(t - sIdx[k]) * (1.f / 2048.f) : 0.f;
        sRel[k][i] = v;
    }
    __syncthreads();

    // layer1: 17 -> 64 + swish(pi/sqrt3)
    for (int task = tid; task < KSEL * 64; task += 256) {
        int k = task >> 6, j = task & 63;
        float acc = b1[j];
#pragma unroll
        for (int i = 0; i < 17; i++) acc += sRel[k][i] * W1[i * 64 + j];
        sH1[k][j] = acc / (1.f + expf(-SCALE_ACT * acc));
    }
    __syncthreads();

    // layer2: 64 -> 64, register-tiled: thread (j = tid&63, kq = tid>>6)
    {
        int j = tid & 63, kq = tid >> 6;    // kq in 0..3, k = kq + 4*i
        float acc[4];
        float bj = b2[j];
#pragma unroll
        for (int i = 0; i < 4; i++) acc[i] = bj;
#pragma unroll 8
        for (int ii = 0; ii < 64; ii++) {
            float w = W2[ii * 64 + j];
#pragma unroll
            for (int i = 0; i < 4; i++) {
                int k = kq + 4 * i;
                float h = (k < KSEL) ? sH1[k][ii] : 0.f;
                acc[i] += h * w;
            }
        }
#pragma unroll
        for (int i = 0; i < 4; i++) {
            int k = kq + 4 * i;
            if (k < KSEL) sH2[k][j] = acc[i];
        }
    }
    __syncthreads();

    // heads: z (2) + mix (1) per k
    if (tid < 45) {
        int k = tid / 3, c = tid - (tid / 3) * 3;
        float acc = (c == 0) ? bc[0] : (c == 1) ? bc[1] : bm[0];
        for (int i = 0; i < 64; i++) {
            float w = (c == 0) ? Wc[i * 2] : (c == 1) ? Wc[i * 2 + 1] : Wm[i];
            acc += sH2[k][i] * w;
        }
        if (c < 2) sZ[k][c] = tanhf(acc); else sMix[k] = acc;
    }
    __syncthreads();

    // softmax over kept + grid coords
    if (tid < 32) {
        float m = (tid < kept) ? sMix[tid] : -INFINITY;
        float mx = m;
#pragma unroll
        for (int o = 16; o; o >>= 1) mx = fmaxf(mx, __shfl_xor_sync(0xffffffffu, mx, o));
        float e = (tid < kept) ? expf(m - mx) : 0.f;
        float se = e;
#pragma unroll
        for (int o = 16; o; o >>= 1) se += __shfl_xor_sync(0xffffffffu, se, o);
        if (tid < KSEL) {
            sWk[tid] = e / se;
            float gx = fminf(fmaxf((sZ[tid][0] + 1.f) * 7.5f, 0.f), 15.f);
            float gy = fminf(fmaxf((sZ[tid][1] + 1.f) * 7.5f, 0.f), 15.f);
            float x0f = floorf(gx), y0f = floorf(gy);
            sX0[tid] = (int)x0f; sY0[tid] = (int)y0f;
            sWx[tid] = gx - x0f; sWy[tid] = gy - y0f;
        }
    }
    __syncthreads();

    // bilinear sample + weighted sum over k (coalesced via transposed palette)
    float acc = 0.f;
    for (int k = 0; k < kept; k++) {
        float wk = sWk[k];
        int x0 = sX0[k], y0 = sY0[k];
        int x1 = min(x0 + 1, 15), y1 = min(y0 + 1, 15);
        float wx = sWx[k], wy = sWy[k];
        float v00 = g_palT[(y0 * 16 + x0) * 256 + tid];
        float v01 = g_palT[(y0 * 16 + x1) * 256 + tid];
        float v10 = g_palT[(y1 * 16 + x0) * 256 + tid];
        float v11 = g_palT[(y1 * 16 + x1) * 256 + tid];
        acc += wk * (v00 * (1.f - wx) * (1.f - wy) + v01 * wx * (1.f - wy)
                   + v10 * (1.f - wx) * wy + v11 * wx * wy);
    }
    g_V[(size_t)(b * Tn + t) * 1024 + r * 256 + tid] = acc;
}

// ---------------- host launcher ----------------
extern "C" void kernel_launch(void* const* d_in, const int* in_sizes, int n_in,
                              void* d_out, int out_size) {
    const float* x       = (const float*)d_in[0];
    const float* Wi      = (const float*)d_in[1];
    const float* Wp      = (const float*)d_in[2];
    const float* W1      = (const float*)d_in[3];
    const float* b1      = (const float*)d_in[4];
    const float* W2      = (const float*)d_in[5];
    const float* b2      = (const float*)d_in[6];
    const float* Wc      = (const float*)d_in[7];
    const float* bc      = (const float*)d_in[8];
    const float* Wm      = (const float*)d_in[9];
    const float* bm      = (const float*)d_in[10];
    const float* palette = (const float*)d_in[11];
    const float* Wo      = (const float*)d_in[12];
    float* out = (float*)d_out;

    float *pI, *pP, *pV;
    cudaGetSymbolAddress((void**)&pI, g_I);
    cudaGetSymbolAddress((void**)&pP, g_P);
    cudaGetSymbolAddress((void**)&pV, g_V);

    k_inv<<<1, 128>>>();
    k_rope_tables<<<Tn, 128>>>();
    k_palT<<<Dm, 256>>>(palette);

    // I = x @ Wi  (4096 x 1024, K=256)
    k_gemm128<<<dim3(8, 32), 256>>>(x, Wi, pI, 256, 256, 1024, 1024, 1.0f);
    // P = x @ Wp  (4096 x 256, K=256) -- SELECTION-CRITICAL: sequential-k,
    // bit-identical to the R9/R12 passing runs. NO split-K here.
    k_gemm_rr<<<dim3(4, 64), 256>>>(x, Wp, pP, 256, 256, 256, 256, 1.0f);

    k_rope_I<<<(Bqn * Tn * BRn * 128) / 256, 256>>>();
    k_rope_P<<<Bqn * Tn, 128>>>();

    k_logits128<<<dim3(16, 16, Bqn * BRn), 256>>>();
    k_topk<<<Bqn * BRn * Tn, 256>>>();
    k_constellation<<<Bqn * BRn * Tn, 256>>>(W1, b1, W2, b2, Wc, bc, Wm, bm);

    // y = 0.25 * V(4096x1024) @ Wo(1024x256) split-K x4 (post-selection, safe)
    k_gemm128sk<<<dim3(2, 32, 4), 256>>>(pV, Wo, 256, 1024, 256, 256);
    k_sumK<<<1024, 256>>>(out, 0.25f, 4096 * 256 / 4);
}

// round 14
// speedup vs baseline: 1.6140x; 1.6140x over previous
#include <cuda_runtime.h>
#include <cmath>

#define Tn 2048
#define Dm 256
#define BRn 4
#define Bqn 2
#define KSEL 15
#define SCALE_ACT 1.8137993642342178f

// ---------------- scratch (device globals; no allocation) ----------------
__device__ float g_inv[128];
__device__ float g_cos[Tn * 128];
__device__ float g_sin[Tn * 128];
__device__ float g_I[Bqn * Tn * BRn * Dm];     // (b, t, r*256+d) rows of 1024
__device__ float g_P[Bqn * Tn * Dm];           // (b, t, d)
__device__ float g_Pn[Bqn * Tn * Dm];          // normalized P rows
__device__ float g_logits[Bqn * BRn * Tn * Tn];// (b*4+r, t, s) 134MB
__device__ int   g_topk[Bqn * BRn * Tn * KSEL];
__device__ float g_V[Bqn * Tn * BRn * Dm];     // (b, t, r*256+d)
__device__ float g_palT[16 * 16 * Dm];         // (y, x, d) transposed palette
__device__ float g_sk[4 * 4096 * 256];         // split-K partials (16MB)

// ---------------- inv frequencies: the ONLY fp64 left ----------------
__global__ void k_inv() {
    int i = threadIdx.x;            // 0..127
    float e = (float)(2 * i) * (1.0f / 256.0f);
    float pw = (float)pow(10000.0, (double)e);
    g_inv[i] = 1.0f / pw;
}

// ---------------- RoPE tables (pure fp32, sincosf <= 2ulp) ----------------
__global__ void k_rope_tables() {
    int t = blockIdx.x;
    int i = threadIdx.x;            // 0..127
    float f = (float)t * g_inv[i];  // f32 outer product, matches numpy
    float s, c;
    sincosf(f, &s, &c);
    g_cos[t * 128 + i] = c;
    g_sin[t * 128 + i] = s;
}

// ---------------- palette transpose (d,y,x) -> (y,x,d) ----------------
__global__ void k_palT(const float* __restrict__ pal) {
    int d = blockIdx.x;             // 0..255
    int p = threadIdx.x;            // 0..255 = y*16+x
    g_palT[p * 256 + d] = pal[d * 256 + p];
}

// ---------------- 64x64 GEMM (sequential-k; used for P: selection-critical) --
__global__ __launch_bounds__(256) void k_gemm_rr(
    const float* __restrict__ A, const float* __restrict__ B, float* __restrict__ C,
    int K, int lda, int ldb, int ldc, float alpha)
{
    __shared__ float As[64][17];
    __shared__ float Bs[64][17];
    int tid = threadIdx.x;
    int m0 = blockIdx.y * 64, n0 = blockIdx.x * 64;
    int tx = tid & 15, ty = tid >> 4;
    float acc[4][4];
#pragma unroll
    for (int i = 0; i < 4; i++)
#pragma unroll
        for (int j = 0; j < 4; j++) acc[i][j] = 0.f;

    int alr = tid >> 2, alc = (tid & 3) << 2;
    int bkk = tid >> 4, bnn = (tid & 15) << 2;

    for (int k0 = 0; k0 < K; k0 += 16) {
        float4 av = *(const float4*)&A[(size_t)(m0 + alr) * lda + k0 + alc];
        As[alr][alc] = av.x; As[alr][alc + 1] = av.y;
        As[alr][alc + 2] = av.z; As[alr][alc + 3] = av.w;
        float4 bv = *(const float4*)&B[(size_t)(k0 + bkk) * ldb + n0 + bnn];
        Bs[bnn][bkk] = bv.x; Bs[bnn + 1][bkk] = bv.y;
        Bs[bnn + 2][bkk] = bv.z; Bs[bnn + 3][bkk] = bv.w;
        __syncthreads();
#pragma unroll
        for (int kk = 0; kk < 16; kk++) {
            float a[4], bb[4];
#pragma unroll
            for (int i = 0; i < 4; i++) a[i] = As[ty + 16 * i][kk];
#pragma unroll
            for (int j = 0; j < 4; j++) bb[j] = Bs[tx + 16 * j][kk];
#pragma unroll
            for (int i = 0; i < 4; i++)
#pragma unroll
                for (int j = 0; j < 4; j++) acc[i][j] += a[i] * bb[j];
        }
        __syncthreads();
    }
#pragma unroll
    for (int i = 0; i < 4; i++)
#pragma unroll
        for (int j = 0; j < 4; j++)
            C[(size_t)(m0 + ty + 16 * i) * ldc + n0 + tx + 16 * j] = acc[i][j] * alpha;
}

// ---------------- 128x128 / 8x8 GEMM, no cross-iter prefetch, 2 blocks/SM --
__global__ __launch_bounds__(256, 2) void k_gemm128(
    const float* __restrict__ A, const float* __restrict__ B, float* __restrict__ C,
    int K, int lda, int ldb, int ldc, float alpha)
{
    __shared__ float As[16][132];
    __shared__ float Bs[16][132];
    int tid = threadIdx.x;
    int tx = tid & 15, ty = tid >> 4;
    int m0 = blockIdx.y * 128, n0 = blockIdx.x * 128;

    int ar = tid >> 2, ac = (tid & 3) << 2;
    int br = tid >> 4, bc = (tid & 15) << 2;

    const float* Ap0 = A + (size_t)(m0 + ar) * lda + ac;
    const float* Ap1 = Ap0 + (size_t)64 * lda;
    const float* Bq  = B + (size_t)br * ldb + n0 + bc;

    float acc[8][8];
#pragma unroll
    for (int i = 0; i < 8; i++)
#pragma unroll
        for (int j = 0; j < 8; j++) acc[i][j] = 0.f;

    int nk = K >> 4;
    for (int kt = 0; kt < nk; kt++) {
        {   // load tile -> smem; registers die before compute
            float4 a0 = *(const float4*)Ap0;
            float4 a1 = *(const float4*)Ap1;
            float4 b0 = *(const float4*)Bq;
            float4 b1 = *(const float4*)(Bq + 64);
            As[ac + 0][ar] = a0.x; As[ac + 1][ar] = a0.y;
            As[ac + 2][ar] = a0.z; As[ac + 3][ar] = a0.w;
            As[ac + 0][ar + 64] = a1.x; As[ac + 1][ar + 64] = a1.y;
            As[ac + 2][ar + 64] = a1.z; As[ac + 3][ar + 64] = a1.w;
            *(float4*)&Bs[br][bc]      = b0;
            *(float4*)&Bs[br][bc + 64] = b1;
        }
        __syncthreads();
#pragma unroll
        for (int kk = 0; kk < 16; kk++) {
            float4 x0 = *(float4*)&As[kk][ty * 8];
            float4 x1 = *(float4*)&As[kk][ty * 8 + 4];
            float4 y0 = *(float4*)&Bs[kk][tx * 8];
            float4 y1 = *(float4*)&Bs[kk][tx * 8 + 4];
            float a[8] = {x0.x, x0.y, x0.z, x0.w, x1.x, x1.y, x1.z, x1.w};
            float bb[8] = {y0.x, y0.y, y0.z, y0.w, y1.x, y1.y, y1.z, y1.w};
#pragma unroll
            for (int i = 0; i < 8; i++)
#pragma unroll
                for (int j = 0; j < 8; j++) acc[i][j] += a[i] * bb[j];
        }
        __syncthreads();
        Ap0 += 16; Ap1 += 16; Bq += (size_t)16 * ldb;
    }
#pragma unroll
    for (int i = 0; i < 8; i++) {
        float* crow = C + (size_t)(m0 + ty * 8 + i) * ldc + n0 + tx * 8;
        float4 o0 = make_float4(acc[i][0] * alpha, acc[i][1] * alpha,
                                acc[i][2] * alpha, acc[i][3] * alpha);
        float4 o1 = make_float4(acc[i][4] * alpha, acc[i][5] * alpha,
                                acc[i][6] * alpha, acc[i][7] * alpha);
        *(float4*)crow = o0;
        *(float4*)(crow + 4) = o1;
    }
}

// ---------------- split-K variant (POST-SELECTION USE ONLY: out GEMM) -----
__global__ __launch_bounds__(256, 2) void k_gemm128sk(
    const float* __restrict__ A, const float* __restrict__ B,
    int Kper, int lda, int ldb, int N)
{
    int z = blockIdx.z;
    A += (size_t)z * Kper;                 // k-offset in A columns
    B += (size_t)z * Kper * ldb;           // k-offset in B rows
    float* C = g_sk + (size_t)z * 4096 * 256;

    __shared__ float As[16][132];
    __shared__ float Bs[16][132];
    int tid = threadIdx.x;
    int tx = tid & 15, ty = tid >> 4;
    int m0 = blockIdx.y * 128, n0 = blockIdx.x * 128;

    int ar = tid >> 2, ac = (tid & 3) << 2;
    int br = tid >> 4, bc = (tid & 15) << 2;

    const float* Ap0 = A + (size_t)(m0 + ar) * lda + ac;
    const float* Ap1 = Ap0 + (size_t)64 * lda;
    const float* Bq  = B + (size_t)br * ldb + n0 + bc;

    float acc[8][8];
#pragma unroll
    for (int i = 0; i < 8; i++)
#pragma unroll
        for (int j = 0; j < 8; j++) acc[i][j] = 0.f;

    int nk = Kper >> 4;
    for (int kt = 0; kt < nk; kt++) {
        {
            float4 a0 = *(const float4*)Ap0;
            float4 a1 = *(const float4*)Ap1;
            float4 b0 = *(const float4*)Bq;
            float4 b1 = *(const float4*)(Bq + 64);
            As[ac + 0][ar] = a0.x; As[ac + 1][ar] = a0.y;
            As[ac + 2][ar] = a0.z; As[ac + 3][ar] = a0.w;
            As[ac + 0][ar + 64] = a1.x; As[ac + 1][ar + 64] = a1.y;
            As[ac + 2][ar + 64] = a1.z; As[ac + 3][ar + 64] = a1.w;
            *(float4*)&Bs[br][bc]      = b0;
            *(float4*)&Bs[br][bc + 64] = b1;
        }
        __syncthreads();
#pragma unroll
        for (int kk = 0; kk < 16; kk++) {
            float4 x0 = *(float4*)&As[kk][ty * 8];
            float4 x1 = *(float4*)&As[kk][ty * 8 + 4];
            float4 y0 = *(float4*)&Bs[kk][tx * 8];
            float4 y1 = *(float4*)&Bs[kk][tx * 8 + 4];
            float a[8] = {x0.x, x0.y, x0.z, x0.w, x1.x, x1.y, x1.z, x1.w};
            float bb[8] = {y0.x, y0.y, y0.z, y0.w, y1.x, y1.y, y1.z, y1.w};
#pragma unroll
            for (int i = 0; i < 8; i++)
#pragma unroll
                for (int j = 0; j < 8; j++) acc[i][j] += a[i] * bb[j];
        }
        __syncthreads();
        Ap0 += 16; Ap1 += 16; Bq += (size_t)16 * ldb;
    }
#pragma unroll
    for (int i = 0; i < 8; i++) {
        float* crow = C + (size_t)(m0 + ty * 8 + i) * N + n0 + tx * 8;
        *(float4*)crow       = *(float4*)&acc[i][0];
        *(float4*)(crow + 4) = *(float4*)&acc[i][4];
    }
}

// ---------------- sum 4 split-K slabs: dst = alpha * sum ----------------
__global__ void k_sumK(float* __restrict__ dst, float alpha, int n4) {
    int i = blockIdx.x * 256 + threadIdx.x;
    if (i >= n4) return;
    const float4* s = (const float4*)g_sk;
    int n = n4;
    float4 v0 = s[i], v1 = s[i + n], v2 = s[i + 2 * n], v3 = s[i + 3 * n];
    float4 o;
    o.x = alpha * (v0.x + v1.x + v2.x + v3.x);
    o.y = alpha * (v0.y + v1.y + v2.y + v3.y);
    o.z = alpha * (v0.z + v1.z + v2.z + v3.z);
    o.w = alpha * (v0.w + v1.w + v2.w + v3.w);
    ((float4*)dst)[i] = o;
}

// ---------------- RoPE on I (elementwise, pairs) ----------------
__global__ void k_rope_I() {
    int p = blockIdx.x * 256 + threadIdx.x;
    int i = p & 127;
    int row = p >> 7;
    int t = (row >> 2) & (Tn - 1);
    float c = g_cos[t * 128 + i], s = g_sin[t * 128 + i];
    float2* ptr = (float2*)g_I;
    size_t o2 = (size_t)(row >> 2) * 512 + (size_t)(row & 3) * 128 + i;
    float2 v = ptr[o2];
    float y1 = v.x * c - v.y * s;
    float y2 = v.x * s + v.y * c;
    ptr[o2] = make_float2(y1, y2);
}

// ---------------- RoPE on P + write normalized Pn ----------------
__global__ void k_rope_P() {
    int row = blockIdx.x;           // b*Tn + t
    int t = row & (Tn - 1);
    int i = threadIdx.x;            // 0..127
    float c = g_cos[t * 128 + i], s = g_sin[t * 128 + i];
    float2* P2 = (float2*)g_P;
    float2* Pn2 = (float2*)g_Pn;
    float2 v = P2[(size_t)row * 128 + i];
    float y1 = v.x * c - v.y * s;
    float y2 = v.x * s + v.y * c;
    float ss = y1 * y1 + y2 * y2;
#pragma unroll
    for (int o = 16; o; o >>= 1) ss += __shfl_xor_sync(0xffffffffu, ss, o);
    __shared__ float sr[4];
    if ((i & 31) == 0) sr[i >> 5] = ss;
    __syncthreads();
    float tot = sr[0] + sr[1] + sr[2] + sr[3];
    float inv = 1.f / fmaxf(sqrtf(tot), 1e-12f);
    P2[(size_t)row * 128 + i] = make_float2(y1, y2);
    Pn2[(size_t)row * 128 + i] = make_float2(y1 * inv, y2 * inv);
}

// ---------------- causal logits: 128x128 tile, 8x8 microtile --------------
__global__ __launch_bounds__(256, 2) void k_logits128() {
    int sT = blockIdx.x, tT = blockIdx.y;
    if (sT > tT) return;
    int bz = blockIdx.z;                        // b*4 + r
    int b = bz >> 2, r = bz & 3;
    const float* A  = g_I + (size_t)b * Tn * 1024 + r * 256;
    const float* Bp = g_P + (size_t)b * Tn * 256;
    float* C = g_logits + (size_t)bz * Tn * Tn;

    __shared__ float As[16][132];
    __shared__ float Bs[16][132];
    int tid = threadIdx.x;
    int tx = tid & 15, ty = tid >> 4;
    int m0 = tT * 128, n0 = sT * 128;

    int ar = tid >> 2, ac = (tid & 3) << 2;

    const float* Ap0 = A  + (size_t)(m0 + ar) * 1024 + ac;
    const float* Ap1 = Ap0 + (size_t)64 * 1024;
    const float* Bq0 = Bp + (size_t)(n0 + ar) * 256 + ac;
    const float* Bq1 = Bq0 + (size_t)64 * 256;

    float acc[8][8];
#pragma unroll
    for (int i = 0; i < 8; i++)
#pragma unroll
        for (int j = 0; j < 8; j++) acc[i][j] = 0.f;

    for (int kt = 0; kt < 16; kt++) {
        {   // load tile -> smem; registers die before compute
            float4 a0 = *(const float4*)Ap0;
            float4 a1 = *(const float4*)Ap1;
            float4 b0 = *(const float4*)Bq0;
            float4 b1 = *(const float4*)Bq1;
            As[ac + 0][ar] = a0.x; As[ac + 1][ar] = a0.y;
            As[ac + 2][ar] = a0.z; As[ac + 3][ar] = a0.w;
            As[ac + 0][ar + 64] = a1.x; As[ac + 1][ar + 64] = a1.y;
            As[ac + 2][ar + 64] = a1.z; As[ac + 3][ar + 64] = a1.w;
            Bs[ac + 0][ar] = b0.x; Bs[ac + 1][ar] = b0.y;
            Bs[ac + 2][ar] = b0.z; Bs[ac + 3][ar] = b0.w;
            Bs[ac + 0][ar + 64] = b1.x; Bs[ac + 1][ar + 64] = b1.y;
            Bs[ac + 2][ar + 64] = b1.z; Bs[ac + 3][ar + 64] = b1.w;
        }
        __syncthreads();
#pragma unroll
        for (int kk = 0; kk < 16; kk++) {
            float4 x0 = *(float4*)&As[kk][ty * 8];
            float4 x1 = *(float4*)&As[kk][ty * 8 + 4];
            float4 y0 = *(float4*)&Bs[kk][tx * 8];
            float4 y1 = *(float4*)&Bs[kk][tx * 8 + 4];
            float a[8] = {x0.x, x0.y, x0.z, x0.w, x1.x, x1.y, x1.z, x1.w};
            float bb[8] = {y0.x, y0.y, y0.z, y0.w, y1.x, y1.y, y1.z, y1.w};
#pragma unroll
            for (int i = 0; i < 8; i++)
#pragma unroll
                for (int j = 0; j < 8; j++) acc[i][j] += a[i] * bb[j];
        }
        __syncthreads();
        Ap0 += 16; Ap1 += 16; Bq0 += 16; Bq1 += 16;
    }
#pragma unroll
    for (int i = 0; i < 8; i++) {
        float* crow = C + (size_t)(m0 + ty * 8 + i) * Tn + n0 + tx * 8;
        float4 o0 = make_float4(acc[i][0] * 0.0625f, acc[i][1] * 0.0625f,
                                acc[i][2] * 0.0625f, acc[i][3] * 0.0625f);
        float4 o1 = make_float4(acc[i][4] * 0.0625f, acc[i][5] * 0.0625f,
                                acc[i][6] * 0.0625f, acc[i][7] * 0.0625f);
        *(float4*)crow = o0;
        *(float4*)(crow + 4) = o1;
    }
}

// ---------------- top-15 v2: register sorting-network + head-merge ----------
// Exactly reproduces jax.lax.top_k order: (value desc, index asc) total order.
#define CE(i, j) { \
    bool sw = (v[j] > v[i]) || (v[j] == v[i] && ix[j] < ix[i]); \
    float tv = sw ? v[j] : v[i];  float uv = sw ? v[i] : v[j]; \
    int   ti = sw ? ix[j] : ix[i]; int ui = sw ? ix[i] : ix[j]; \
    v[i] = tv; v[j] = uv; ix[i] = ti; ix[j] = ui; }

__global__ __launch_bounds__(256) void k_topk() {
    __shared__ float svv[2][8];
    __shared__ int   svi[2][8];
    int bid = blockIdx.x;           // br*Tn + t
    int t = bid & (Tn - 1);
    const float* row = g_logits + (size_t)bid * Tn;
    int L = t + 1;                  // causal: only s <= t valid
    int tid = threadIdx.x;
    int lane = tid & 31, wid = tid >> 5;

    // load up to 8 strided elements into registers
    float v[8]; int ix[8];
#pragma unroll
    for (int q = 0; q < 8; q++) {
        int i = tid + 256 * q;
        bool ok = (i < L);
        v[q]  = ok ? row[i] : -INFINITY;
        ix[q] = ok ? i : 0x7fffffff;
    }
    // Batcher odd-even merge sort, 8 elements, 19 CEs (desc value, asc index)
    CE(0,1) CE(2,3) CE(4,5) CE(6,7)
    CE(0,2) CE(1,3) CE(4,6) CE(5,7)
    CE(1,2) CE(5,6)
    CE(0,4) CE(1,5) CE(2,6) CE(3,7)
    CE(2,4) CE(3,5)
    CE(1,2) CE(3,4) CE(5,6)

    for (int it = 0; it < KSEL; it++) {
        float bv = v[0]; int bi = ix[0];
#pragma unroll
        for (int o = 16; o; o >>= 1) {
            float ov = __shfl_down_sync(0xffffffffu, bv, o);
            int   oi = __shfl_down_sync(0xffffffffu, bi, o);
            if (ov > bv || (ov == bv && oi < bi)) { bv = ov; bi = oi; }
        }
        int buf = it & 1;
        if (lane == 0) { svv[buf][wid] = bv; svi[buf][wid] = bi; }
        __syncthreads();
        float fb = svv[buf][0]; int fi = svi[buf][0];
#pragma unroll
        for (int w = 1; w < 8; w++) {
            float wv = svv[buf][w]; int wi = svi[buf][w];
            if (wv > fb || (wv == fb && wi < fi)) { fb = wv; fi = wi; }
        }
        if (tid == 0) g_topk[bid * KSEL + it] = (fi == 0x7fffffff) ? 0 : fi;
        if (ix[0] == fi) {          // unique owner pops its head
#pragma unroll
            for (int q = 0; q < 7; q++) { v[q] = v[q + 1]; ix[q] = ix[q + 1]; }
            v[7] = -INFINITY; ix[7] = 0x7fffffff;
        }
    }
}
#undef CE

// ---------------- constellation v2: register-outer-product gram ----------
__global__ __launch_bounds__(256) void k_constellation(
    const float* __restrict__ W1, const float* __restrict__ b1,
    const float* __restrict__ W2, const float* __restrict__ b2,
    const float* __restrict__ Wc, const float* __restrict__ bc,
    const float* __restrict__ Wm, const float* __restrict__ bm)
{
    __shared__ float sM[16][Dm];       // rows 0..14 = Pn_sel, row 15 = I_n
    __shared__ float sS[16][17];       // full 16x16 gram (incl. I row)
    __shared__ float sRel[KSEL][18];
    __shared__ float sH1[KSEL][64];
    __shared__ float sH2[KSEL][66];
    __shared__ int   sIdx[KSEL];
    __shared__ float sZ[KSEL][2];
    __shared__ float sMix[KSEL];
    __shared__ float sWk[KSEL];
    __shared__ int   sX0[KSEL], sY0[KSEL];
    __shared__ float sWx[KSEL], sWy[KSEL];
    __shared__ float sred[8];

    int tid = threadIdx.x;
    int bid = blockIdx.x;
    int t = bid & (Tn - 1);
    int br = bid >> 11;
    int b = br >> 2;
    int r = br & 3;
    int kept = min(t + 1, KSEL);
    int wid = tid >> 5, lane = tid & 31;

    if (tid < KSEL) sIdx[tid] = (tid < kept) ? g_topk[bid * KSEL + tid] : 0;
    __syncthreads();

    // selected normalized P rows (zeroed beyond kept)
    for (int e = tid; e < KSEL * Dm; e += 256) {
        int k = e >> 8, d = e & 255;
        sM[k][d] = (k < kept) ? g_Pn[(size_t)(b * Tn + sIdx[k]) * Dm + d] : 0.f;
    }
    // normalize I row into sM[15]
    float iv = g_I[(size_t)(b * Tn + t) * 1024 + r * 256 + tid];
    float ss = iv * iv;
#pragma unroll
    for (int o = 16; o; o >>= 1) ss += __shfl_xor_sync(0xffffffffu, ss, o);
    if ((tid & 31) == 0) sred[tid >> 5] = ss;
    __syncthreads();
    float tot = 0.f;
#pragma unroll
    for (int w = 0; w < 8; w++) tot += sred[w];
    float inv = 1.f / fmaxf(sqrtf(tot), 1e-12f);
    sM[15][tid] = iv * inv;
    __syncthreads();

    // ---- gram: warp w computes rows 2w, 2w+1 of S = M M^T (16x16) ----
    {
        int k0 = 2 * wid, k1 = 2 * wid + 1;
        float p0[16], p1[16];
#pragma unroll
        for (int j = 0; j < 16; j++) { p0[j] = 0.f; p1[j] = 0.f; }
#pragma unroll
        for (int q = 0; q < 8; q++) {
            int d = q * 32 + lane;
            float m[16];
#pragma unroll
            for (int i = 0; i < 16; i++) m[i] = sM[i][d];
            float a0 = m[k0 & 15];
            float a1 = m[k1 & 15];
#pragma unroll
            for (int j = 0; j < 16; j++) {
                p0[j] += a0 * m[j];
                p1[j] += a1 * m[j];
            }
        }
#pragma unroll
        for (int j = 0; j < 16; j++) {
            float s0 = p0[j], s1 = p1[j];
#pragma unroll
            for (int o = 16; o; o >>= 1) {
                s0 += __shfl_xor_sync(0xffffffffu, s0, o);
                s1 += __shfl_xor_sync(0xffffffffu, s1, o);
            }
            if (lane == j) { sS[k0][j] = s0; sS[k1][j] = s1; }
        }
    }
    __syncthreads();

    // build rel features (15 x 17)
    if (tid < KSEL * 17) {
        int k = tid / 17, i = tid - k * 17;
        float v;
        if (i < 15)       v = fminf(fmaxf(sS[k][i], -1.f), 1.f);
        else if (i == 15) v = fminf(fmaxf(sS[15][k], -1.f), 1.f);
        else              v = (k < kept) ? (float)(t - sIdx[k]) * (1.f / 2048.f) : 0.f;
        sRel[k][i] = v;
    }
    __syncthreads();

    // layer1: 17 -> 64 + swish(pi/sqrt3)
    for (int task = tid; task < KSEL * 64; task += 256) {
        int k = task >> 6, j = task & 63;
        float acc = b1[j];
#pragma unroll
        for (int i = 0; i < 17; i++) acc += sRel[k][i] * W1[i * 64 + j];
        sH1[k][j] = acc / (1.f + expf(-SCALE_ACT * acc));
    }
    __syncthreads();

    // layer2: 64 -> 64, register-tiled: thread (j = tid&63, kq = tid>>6)
    {
        int j = tid & 63, kq = tid >> 6;    // kq in 0..3, k = kq + 4*i
        float acc[4];
        float bj = b2[j];
#pragma unroll
        for (int i = 0; i < 4; i++) acc[i] = bj;
#pragma unroll 8
        for (int ii = 0; ii < 64; ii++) {
            float w = W2[ii * 64 + j];
#pragma unroll
            for (int i = 0; i < 4; i++) {
                int k = kq + 4 * i;
                float h = (k < KSEL) ? sH1[k][ii] : 0.f;
                acc[i] += h * w;
            }
        }
#pragma unroll
        for (int i = 0; i < 4; i++) {
            int k = kq + 4 * i;
            if (k < KSEL) sH2[k][j] = acc[i];
        }
    }
    __syncthreads();

    // heads: z (2) + mix (1) per k
    if (tid < 45) {
        int k = tid / 3, c = tid - (tid / 3) * 3;
        float acc = (c == 0) ? bc[0] : (c == 1) ? bc[1] : bm[0];
        for (int i = 0; i < 64; i++) {
            float w = (c == 0) ? Wc[i * 2] : (c == 1) ? Wc[i * 2 + 1] : Wm[i];
            acc += sH2[k][i] * w;
        }
        if (c < 2) sZ[k][c] = tanhf(acc); else sMix[k] = acc;
    }
    __syncthreads();

    // softmax over kept + grid coords
    if (tid < 32) {
        float m = (tid < kept) ? sMix[tid] : -INFINITY;
        float mx = m;
#pragma unroll
        for (int o = 16; o; o >>= 1) mx = fmaxf(mx, __shfl_xor_sync(0xffffffffu, mx, o));
        float e = (tid < kept) ? expf(m - mx) : 0.f;
        float se = e;
#pragma unroll
        for (int o = 16; o; o >>= 1) se += __shfl_xor_sync(0xffffffffu, se, o);
        if (tid < KSEL) {
            sWk[tid] = e / se;
            float gx = fminf(fmaxf((sZ[tid][0] + 1.f) * 7.5f, 0.f), 15.f);
            float gy = fminf(fmaxf((sZ[tid][1] + 1.f) * 7.5f, 0.f), 15.f);
            float x0f = floorf(gx), y0f = floorf(gy);
            sX0[tid] = (int)x0f; sY0[tid] = (int)y0f;
            sWx[tid] = gx - x0f; sWy[tid] = gy - y0f;
        }
    }
    __syncthreads();

    // bilinear sample + weighted sum over k (coalesced via transposed palette)
    float acc = 0.f;
    for (int k = 0; k < kept; k++) {
        float wk = sWk[k];
        int x0 = sX0[k], y0 = sY0[k];
        int x1 = min(x0 + 1, 15), y1 = min(y0 + 1, 15);
        float wx = sWx[k], wy = sWy[k];
        float v00 = g_palT[(y0 * 16 + x0) * 256 + tid];
        float v01 = g_palT[(y0 * 16 + x1) * 256 + tid];
        float v10 = g_palT[(y1 * 16 + x0) * 256 + tid];
        float v11 = g_palT[(y1 * 16 + x1) * 256 + tid];
        acc += wk * (v00 * (1.f - wx) * (1.f - wy) + v01 * wx * (1.f - wy)
                   + v10 * (1.f - wx) * wy + v11 * wx * wy);
    }
    g_V[(size_t)(b * Tn + t) * 1024 + r * 256 + tid] = acc;
}

// ---------------- host launcher ----------------
extern "C" void kernel_launch(void* const* d_in, const int* in_sizes, int n_in,
                              void* d_out, int out_size) {
    const float* x       = (const float*)d_in[0];
    const float* Wi      = (const float*)d_in[1];
    const float* Wp      = (const float*)d_in[2];
    const float* W1      = (const float*)d_in[3];
    const float* b1      = (const float*)d_in[4];
    const float* W2      = (const float*)d_in[5];
    const float* b2      = (const float*)d_in[6];
    const float* Wc      = (const float*)d_in[7];
    const float* bc      = (const float*)d_in[8];
    const float* Wm      = (const float*)d_in[9];
    const float* bm      = (const float*)d_in[10];
    const float* palette = (const float*)d_in[11];
    const float* Wo      = (const float*)d_in[12];
    float* out = (float*)d_out;

    float *pI, *pP, *pV;
    cudaGetSymbolAddress((void**)&pI, g_I);
    cudaGetSymbolAddress((void**)&pP, g_P);
    cudaGetSymbolAddress((void**)&pV, g_V);

    k_inv<<<1, 128>>>();
    k_rope_tables<<<Tn, 128>>>();
    k_palT<<<Dm, 256>>>(palette);

    // I = x @ Wi  (4096 x 1024, K=256)
    k_gemm128<<<dim3(8, 32), 256>>>(x, Wi, pI, 256, 256, 1024, 1024, 1.0f);
    // P = x @ Wp  (4096 x 256, K=256) -- SELECTION-CRITICAL: sequential-k,
    // bit-identical to the R9/R12 passing runs. NO split-K here.
    k_gemm_rr<<<dim3(4, 64), 256>>>(x, Wp, pP, 256, 256, 256, 256, 1.0f);

    k_rope_I<<<(Bqn * Tn * BRn * 128) / 256, 256>>>();
    k_rope_P<<<Bqn * Tn, 128>>>();

    k_logits128<<<dim3(16, 16, Bqn * BRn), 256>>>();
    k_topk<<<Bqn * BRn * Tn, 256>>>();
    k_constellation<<<Bqn * BRn * Tn, 256>>>(W1, b1, W2, b2, Wc, bc, Wm, bm);

    // y = 0.25 * V(4096x1024) @ Wo(1024x256) split-K x4 (post-selection, safe)
    k_gemm128sk<<<dim3(2, 32, 4), 256>>>(pV, Wo, 256, 1024, 256, 256);
    k_sumK<<<1024, 256>>>(out, 0.25f, 4096 * 256 / 4);
}

// round 16
// speedup vs baseline: 1.8142x; 1.1240x over previous
#include <cuda_runtime.h>
#include <cmath>

#define Tn 2048
#define Dm 256
#define BRn 4
#define Bqn 2
#define KSEL 15
#define SCALE_ACT 1.8137993642342178f

// ---------------- scratch (device globals; no allocation) ----------------
__device__ float g_inv[128];
__device__ float g_cos[Tn * 128];
__device__ float g_sin[Tn * 128];
__device__ float g_I[Bqn * Tn * BRn * Dm];     // (b, t, r*256+d) rows of 1024
__device__ float g_P[Bqn * Tn * Dm];           // (b, t, d)
__device__ float g_Pn[Bqn * Tn * Dm];          // normalized P rows
__device__ float g_logits[Bqn * BRn * Tn * Tn];// (b*4+r, t, s) 134MB
__device__ int   g_topk[Bqn * BRn * Tn * KSEL];
__device__ float g_V[Bqn * Tn * BRn * Dm];     // (b, t, r*256+d)
__device__ float g_palT[16 * 16 * Dm];         // (y, x, d) transposed palette
__device__ float g_sk[4 * 4096 * 256];         // split-K partials (16MB)

// ---------------- inv frequencies: the ONLY fp64 left ----------------
__global__ void k_inv() {
    int i = threadIdx.x;            // 0..127
    float e = (float)(2 * i) * (1.0f / 256.0f);
    float pw = (float)pow(10000.0, (double)e);
    g_inv[i] = 1.0f / pw;
}

// ---------------- RoPE tables (pure fp32, sincosf <= 2ulp) ----------------
__global__ void k_rope_tables() {
    int t = blockIdx.x;
    int i = threadIdx.x;            // 0..127
    float f = (float)t * g_inv[i];  // f32 outer product, matches numpy
    float s, c;
    sincosf(f, &s, &c);
    g_cos[t * 128 + i] = c;
    g_sin[t * 128 + i] = s;
}

// ---------------- palette transpose (d,y,x) -> (y,x,d) ----------------
__global__ void k_palT(const float* __restrict__ pal) {
    int d = blockIdx.x;             // 0..255
    int p = threadIdx.x;            // 0..255 = y*16+x
    g_palT[p * 256 + d] = pal[d * 256 + p];
}

// ---------------- 64x64 GEMM (sequential-k; used for P: selection-critical) --
__global__ __launch_bounds__(256) void k_gemm_rr(
    const float* __restrict__ A, const float* __restrict__ B, float* __restrict__ C,
    int K, int lda, int ldb, int ldc, float alpha)
{
    __shared__ float As[64][17];
    __shared__ float Bs[64][17];
    int tid = threadIdx.x;
    int m0 = blockIdx.y * 64, n0 = blockIdx.x * 64;
    int tx = tid & 15, ty = tid >> 4;
    float acc[4][4];
#pragma unroll
    for (int i = 0; i < 4; i++)
#pragma unroll
        for (int j = 0; j < 4; j++) acc[i][j] = 0.f;

    int alr = tid >> 2, alc = (tid & 3) << 2;
    int bkk = tid >> 4, bnn = (tid & 15) << 2;

    for (int k0 = 0; k0 < K; k0 += 16) {
        float4 av = *(const float4*)&A[(size_t)(m0 + alr) * lda + k0 + alc];
        As[alr][alc] = av.x; As[alr][alc + 1] = av.y;
        As[alr][alc + 2] = av.z; As[alr][alc + 3] = av.w;
        float4 bv = *(const float4*)&B[(size_t)(k0 + bkk) * ldb + n0 + bnn];
        Bs[bnn][bkk] = bv.x; Bs[bnn + 1][bkk] = bv.y;
        Bs[bnn + 2][bkk] = bv.z; Bs[bnn + 3][bkk] = bv.w;
        __syncthreads();
#pragma unroll
        for (int kk = 0; kk < 16; kk++) {
            float a[4], bb[4];
#pragma unroll
            for (int i = 0; i < 4; i++) a[i] = As[ty + 16 * i][kk];
#pragma unroll
            for (int j = 0; j < 4; j++) bb[j] = Bs[tx + 16 * j][kk];
#pragma unroll
            for (int i = 0; i < 4; i++)
#pragma unroll
                for (int j = 0; j < 4; j++) acc[i][j] += a[i] * bb[j];
        }
        __syncthreads();
    }
#pragma unroll
    for (int i = 0; i < 4; i++)
#pragma unroll
        for (int j = 0; j < 4; j++)
            C[(size_t)(m0 + ty + 16 * i) * ldc + n0 + tx + 16 * j] = acc[i][j] * alpha;
}

// ---------------- 128x128 / 8x8 GEMM (R12 prefetch version) ----
__global__ __launch_bounds__(256) void k_gemm128(
    const float* __restrict__ A, const float* __restrict__ B, float* __restrict__ C,
    int K, int lda, int ldb, int ldc, float alpha)
{
    __shared__ float As[16][132];
    __shared__ float Bs[16][132];
    int tid = threadIdx.x;
    int tx = tid & 15, ty = tid >> 4;
    int m0 = blockIdx.y * 128, n0 = blockIdx.x * 128;

    int ar = tid >> 2, ac = (tid & 3) << 2;
    int br = tid >> 4, bc = (tid & 15) << 2;

    const float* Ap0 = A + (size_t)(m0 + ar) * lda + ac;
    const float* Ap1 = Ap0 + (size_t)64 * lda;
    const float* Bq  = B + (size_t)br * ldb + n0 + bc;

    float4 a0 = *(const float4*)Ap0;
    float4 a1 = *(const float4*)Ap1;
    float4 b0 = *(const float4*)Bq;
    float4 b1 = *(const float4*)(Bq + 64);

    float acc[8][8];
#pragma unroll
    for (int i = 0; i < 8; i++)
#pragma unroll
        for (int j = 0; j < 8; j++) acc[i][j] = 0.f;

    int nk = K >> 4;
    for (int kt = 0; kt < nk; kt++) {
        As[ac + 0][ar] = a0.x; As[ac + 1][ar] = a0.y;
        As[ac + 2][ar] = a0.z; As[ac + 3][ar] = a0.w;
        As[ac + 0][ar + 64] = a1.x; As[ac + 1][ar + 64] = a1.y;
        As[ac + 2][ar + 64] = a1.z; As[ac + 3][ar + 64] = a1.w;
        *(float4*)&Bs[br][bc]      = b0;
        *(float4*)&Bs[br][bc + 64] = b1;
        __syncthreads();
        if (kt + 1 < nk) {
            Ap0 += 16; Ap1 += 16; Bq += (size_t)16 * ldb;
            a0 = *(const float4*)Ap0;
            a1 = *(const float4*)Ap1;
            b0 = *(const float4*)Bq;
            b1 = *(const float4*)(Bq + 64);
        }
#pragma unroll
        for (int kk = 0; kk < 16; kk++) {
            float4 x0 = *(float4*)&As[kk][ty * 8];
            float4 x1 = *(float4*)&As[kk][ty * 8 + 4];
            float4 y0 = *(float4*)&Bs[kk][tx * 8];
            float4 y1 = *(float4*)&Bs[kk][tx * 8 + 4];
            float a[8] = {x0.x, x0.y, x0.z, x0.w, x1.x, x1.y, x1.z, x1.w};
            float bb[8] = {y0.x, y0.y, y0.z, y0.w, y1.x, y1.y, y1.z, y1.w};
#pragma unroll
            for (int i = 0; i < 8; i++)
#pragma unroll
                for (int j = 0; j < 8; j++) acc[i][j] += a[i] * bb[j];
        }
        __syncthreads();
    }
#pragma unroll
    for (int i = 0; i < 8; i++) {
        float* crow = C + (size_t)(m0 + ty * 8 + i) * ldc + n0 + tx * 8;
        float4 o0 = make_float4(acc[i][0] * alpha, acc[i][1] * alpha,
                                acc[i][2] * alpha, acc[i][3] * alpha);
        float4 o1 = make_float4(acc[i][4] * alpha, acc[i][5] * alpha,
                                acc[i][6] * alpha, acc[i][7] * alpha);
        *(float4*)crow = o0;
        *(float4*)(crow + 4) = o1;
    }
}

// ---------------- split-K variant (POST-SELECTION USE ONLY: out GEMM) -----
__global__ __launch_bounds__(256) void k_gemm128sk(
    const float* __restrict__ A, const float* __restrict__ B,
    int Kper, int lda, int ldb, int N)
{
    int z = blockIdx.z;
    A += (size_t)z * Kper;
    B += (size_t)z * Kper * ldb;
    float* C = g_sk + (size_t)z * 4096 * 256;

    __shared__ float As[16][132];
    __shared__ float Bs[16][132];
    int tid = threadIdx.x;
    int tx = tid & 15, ty = tid >> 4;
    int m0 = blockIdx.y * 128, n0 = blockIdx.x * 128;

    int ar = tid >> 2, ac = (tid & 3) << 2;
    int br = tid >> 4, bc = (tid & 15) << 2;

    const float* Ap0 = A + (size_t)(m0 + ar) * lda + ac;
    const float* Ap1 = Ap0 + (size_t)64 * lda;
    const float* Bq  = B + (size_t)br * ldb + n0 + bc;

    float4 a0 = *(const float4*)Ap0;
    float4 a1 = *(const float4*)Ap1;
    float4 b0 = *(const float4*)Bq;
    float4 b1 = *(const float4*)(Bq + 64);

    float acc[8][8];
#pragma unroll
    for (int i = 0; i < 8; i++)
#pragma unroll
        for (int j = 0; j < 8; j++) acc[i][j] = 0.f;

    int nk = Kper >> 4;
    for (int kt = 0; kt < nk; kt++) {
        As[ac + 0][ar] = a0.x; As[ac + 1][ar] = a0.y;
        As[ac + 2][ar] = a0.z; As[ac + 3][ar] = a0.w;
        As[ac + 0][ar + 64] = a1.x; As[ac + 1][ar + 64] = a1.y;
        As[ac + 2][ar + 64] = a1.z; As[ac + 3][ar + 64] = a1.w;
        *(float4*)&Bs[br][bc]      = b0;
        *(float4*)&Bs[br][bc + 64] = b1;
        __syncthreads();
        if (kt + 1 < nk) {
            Ap0 += 16; Ap1 += 16; Bq += (size_t)16 * ldb;
            a0 = *(const float4*)Ap0;
            a1 = *(const float4*)Ap1;
            b0 = *(const float4*)Bq;
            b1 = *(const float4*)(Bq + 64);
        }
#pragma unroll
        for (int kk = 0; kk < 16; kk++) {
            float4 x0 = *(float4*)&As[kk][ty * 8];
            float4 x1 = *(float4*)&As[kk][ty * 8 + 4];
            float4 y0 = *(float4*)&Bs[kk][tx * 8];
            float4 y1 = *(float4*)&Bs[kk][tx * 8 + 4];
            float a[8] = {x0.x, x0.y, x0.z, x0.w, x1.x, x1.y, x1.z, x1.w};
            float bb[8] = {y0.x, y0.y, y0.z, y0.w, y1.x, y1.y, y1.z, y1.w};
#pragma unroll
            for (int i = 0; i < 8; i++)
#pragma unroll
                for (int j = 0; j < 8; j++) acc[i][j] += a[i] * bb[j];
        }
        __syncthreads();
    }
#pragma unroll
    for (int i = 0; i < 8; i++) {
        float* crow = C + (size_t)(m0 + ty * 8 + i) * N + n0 + tx * 8;
        *(float4*)crow       = *(float4*)&acc[i][0];
        *(float4*)(crow + 4) = *(float4*)&acc[i][4];
    }
}

// ---------------- sum 4 split-K slabs: dst = alpha * sum ----------------
__global__ void k_sumK(float* __restrict__ dst, float alpha, int n4) {
    int i = blockIdx.x * 256 + threadIdx.x;
    if (i >= n4) return;
    const float4* s = (const float4*)g_sk;
    int n = n4;
    float4 v0 = s[i], v1 = s[i + n], v2 = s[i + 2 * n], v3 = s[i + 3 * n];
    float4 o;
    o.x = alpha * (v0.x + v1.x + v2.x + v3.x);
    o.y = alpha * (v0.y + v1.y + v2.y + v3.y);
    o.z = alpha * (v0.z + v1.z + v2.z + v3.z);
    o.w = alpha * (v0.w + v1.w + v2.w + v3.w);
    ((float4*)dst)[i] = o;
}

// ---------------- RoPE on I (elementwise, pairs) ----------------
__global__ void k_rope_I() {
    int p = blockIdx.x * 256 + threadIdx.x;
    int i = p & 127;
    int row = p >> 7;
    int t = (row >> 2) & (Tn - 1);
    float c = g_cos[t * 128 + i], s = g_sin[t * 128 + i];
    float2* ptr = (float2*)g_I;
    size_t o2 = (size_t)(row >> 2) * 512 + (size_t)(row & 3) * 128 + i;
    float2 v = ptr[o2];
    float y1 = v.x * c - v.y * s;
    float y2 = v.x * s + v.y * c;
    ptr[o2] = make_float2(y1, y2);
}

// ---------------- RoPE on P + write normalized Pn ----------------
__global__ void k_rope_P() {
    int row = blockIdx.x;           // b*Tn + t
    int t = row & (Tn - 1);
    int i = threadIdx.x;            // 0..127
    float c = g_cos[t * 128 + i], s = g_sin[t * 128 + i];
    float2* P2 = (float2*)g_P;
    float2* Pn2 = (float2*)g_Pn;
    float2 v = P2[(size_t)row * 128 + i];
    float y1 = v.x * c - v.y * s;
    float y2 = v.x * s + v.y * c;
    float ss = y1 * y1 + y2 * y2;
#pragma unroll
    for (int o = 16; o; o >>= 1) ss += __shfl_xor_sync(0xffffffffu, ss, o);
    __shared__ float sr[4];
    if ((i & 31) == 0) sr[i >> 5] = ss;
    __syncthreads();
    float tot = sr[0] + sr[1] + sr[2] + sr[3];
    float inv = 1.f / fmaxf(sqrtf(tot), 1e-12f);
    P2[(size_t)row * 128 + i] = make_float2(y1, y2);
    Pn2[(size_t)row * 128 + i] = make_float2(y1 * inv, y2 * inv);
}

// ---------------- causal logits: 128x128 tile (R12 prefetch version) ------
__global__ __launch_bounds__(256) void k_logits128() {
    int sT = blockIdx.x, tT = blockIdx.y;
    if (sT > tT) return;
    int bz = blockIdx.z;                        // b*4 + r
    int b = bz >> 2, r = bz & 3;
    const float* A  = g_I + (size_t)b * Tn * 1024 + r * 256;
    const float* Bp = g_P + (size_t)b * Tn * 256;
    float* C = g_logits + (size_t)bz * Tn * Tn;

    __shared__ float As[16][132];
    __shared__ float Bs[16][132];
    int tid = threadIdx.x;
    int tx = tid & 15, ty = tid >> 4;
    int m0 = tT * 128, n0 = sT * 128;

    int ar = tid >> 2, ac = (tid & 3) << 2;

    const float* Ap0 = A  + (size_t)(m0 + ar) * 1024 + ac;
    const float* Ap1 = Ap0 + (size_t)64 * 1024;
    const float* Bq0 = Bp + (size_t)(n0 + ar) * 256 + ac;
    const float* Bq1 = Bq0 + (size_t)64 * 256;

    float4 a0 = *(const float4*)Ap0;
    float4 a1 = *(const float4*)Ap1;
    float4 b0 = *(const float4*)Bq0;
    float4 b1 = *(const float4*)Bq1;

    float acc[8][8];
#pragma unroll
    for (int i = 0; i < 8; i++)
#pragma unroll
        for (int j = 0; j < 8; j++) acc[i][j] = 0.f;

    for (int kt = 0; kt < 16; kt++) {
        As[ac + 0][ar] = a0.x; As[ac + 1][ar] = a0.y;
        As[ac + 2][ar] = a0.z; As[ac + 3][ar] = a0.w;
        As[ac + 0][ar + 64] = a1.x; As[ac + 1][ar + 64] = a1.y;
        As[ac + 2][ar + 64] = a1.z; As[ac + 3][ar + 64] = a1.w;
        Bs[ac + 0][ar] = b0.x; Bs[ac + 1][ar] = b0.y;
        Bs[ac + 2][ar] = b0.z; Bs[ac + 3][ar] = b0.w;
        Bs[ac + 0][ar + 64] = b1.x; Bs[ac + 1][ar + 64] = b1.y;
        Bs[ac + 2][ar + 64] = b1.z; Bs[ac + 3][ar + 64] = b1.w;
        __syncthreads();
        if (kt < 15) {
            Ap0 += 16; Ap1 += 16; Bq0 += 16; Bq1 += 16;
            a0 = *(const float4*)Ap0;
            a1 = *(const float4*)Ap1;
            b0 = *(const float4*)Bq0;
            b1 = *(const float4*)Bq1;
        }
#pragma unroll
        for (int kk = 0; kk < 16; kk++) {
            float4 x0 = *(float4*)&As[kk][ty * 8];
            float4 x1 = *(float4*)&As[kk][ty * 8 + 4];
            float4 y0 = *(float4*)&Bs[kk][tx * 8];
            float4 y1 = *(float4*)&Bs[kk][tx * 8 + 4];
            float a[8] = {x0.x, x0.y, x0.z, x0.w, x1.x, x1.y, x1.z, x1.w};
            float bb[8] = {y0.x, y0.y, y0.z, y0.w, y1.x, y1.y, y1.z, y1.w};
#pragma unroll
            for (int i = 0; i < 8; i++)
#pragma unroll
                for (int j = 0; j < 8; j++) acc[i][j] += a[i] * bb[j];
        }
        __syncthreads();
    }
#pragma unroll
    for (int i = 0; i < 8; i++) {
        float* crow = C + (size_t)(m0 + ty * 8 + i) * Tn + n0 + tx * 8;
        float4 o0 = make_float4(acc[i][0] * 0.0625f, acc[i][1] * 0.0625f,
                                acc[i][2] * 0.0625f, acc[i][3] * 0.0625f);
        float4 o1 = make_float4(acc[i][4] * 0.0625f, acc[i][5] * 0.0625f,
                                acc[i][6] * 0.0625f, acc[i][7] * 0.0625f);
        *(float4*)crow = o0;
        *(float4*)(crow + 4) = o1;
    }
}

// ---------------- top-15 per (b,r,t) (R12 v1, proven) ----------------
__global__ __launch_bounds__(256) void k_topk() {
    __shared__ float sv[Tn];
    __shared__ float rv[8];
    __shared__ int   ri[8];
    int bid = blockIdx.x;           // br*Tn + t
    int t = bid & (Tn - 1);
    const float* row = g_logits + (size_t)bid * Tn;
    int L = t + 1;
    int tid = threadIdx.x;
    for (int i = tid; i < L; i += 256) sv[i] = row[i];
    __syncthreads();
    int kc = min(L, KSEL);
    for (int it = 0; it < kc; it++) {
        float bv = -INFINITY; int bi = 0;
        for (int i = tid; i < L; i += 256) {
            float v = sv[i];
            if (v > bv) { bv = v; bi = i; }
        }
#pragma unroll
        for (int o = 16; o; o >>= 1) {
            float ov = __shfl_down_sync(0xffffffffu, bv, o);
            int   oi = __shfl_down_sync(0xffffffffu, bi, o);
            if (ov > bv || (ov == bv && oi < bi)) { bv = ov; bi = oi; }
        }
        if ((tid & 31) == 0) { rv[tid >> 5] = bv; ri[tid >> 5] = bi; }
        __syncthreads();
        if (tid == 0) {
            float fb = rv[0]; int fi = ri[0];
            for (int w = 1; w < 8; w++)
                if (rv[w] > fb || (rv[w] == fb && ri[w] < fi)) { fb = rv[w]; fi = ri[w]; }
            g_topk[bid * KSEL + it] = fi;
            sv[fi] = -INFINITY;
        }
        __syncthreads();
    }
    if (tid == 0)
        for (int it = kc; it < KSEL; it++) g_topk[bid * KSEL + it] = 0;
}

// ---------------- constellation v3: smem weights + vectorized I/O --------
__global__ __launch_bounds__(256) void k_constellation(
    const float* __restrict__ W1, const float* __restrict__ b1,
    const float* __restrict__ W2, const float* __restrict__ b2,
    const float* __restrict__ Wc, const float* __restrict__ bc,
    const float* __restrict__ Wm, const float* __restrict__ bm)
{
    __shared__ float sM[16][Dm];       // rows 0..14 = Pn_sel, row 15 = I_n
    __shared__ float sS[16][17];       // full 16x16 gram (incl. I row)
    __shared__ float sRel[KSEL][18];
    __shared__ float sH1[KSEL][64];
    __shared__ float sH2[KSEL][66];
    __shared__ float sW2[64 * 64];
    __shared__ float sb2[64];
    __shared__ float sWc[128];
    __shared__ float sWm[64];
    __shared__ float sbc2[2];
    __shared__ float sbm1[1];
    __shared__ int   sIdx[KSEL];
    __shared__ float sZ[KSEL][2];
    __shared__ float sMix[KSEL];
    __shared__ float sWk[KSEL];
    __shared__ int   sX0[KSEL], sY0[KSEL];
    __shared__ float sWx[KSEL], sWy[KSEL];
    __shared__ float sred[8];

    int tid = threadIdx.x;
    int bid = blockIdx.x;
    int t = bid & (Tn - 1);
    int br = bid >> 11;
    int b = br >> 2;
    int r = br & 3;
    int kept = min(t + 1, KSEL);
    int wid = tid >> 5, lane = tid & 31;

    // coop-stage weights into smem (overlaps with sIdx write)
    {
        const float4* W24 = (const float4*)W2;
        float4* sW24 = (float4*)sW2;
#pragma unroll
        for (int q = 0; q < 4; q++) sW24[tid + 256 * q] = W24[tid + 256 * q];
        if (tid < 64)                  sb2[tid] = b2[tid];
        else if (tid < 192)            sWc[tid - 64] = Wc[tid - 64];
        else                           sWm[tid - 192] = Wm[tid - 192];
        if (tid == 0) { sbc2[0] = bc[0]; sbc2[1] = bc[1]; sbm1[0] = bm[0]; }
    }
    if (tid < KSEL) sIdx[tid] = (tid < kept) ? g_topk[bid * KSEL + tid] : 0;
    __syncthreads();

    // selected normalized P rows via float4 (zeroed beyond kept)
    {
        const float4* Pn4 = (const float4*)g_Pn;
        for (int e = tid; e < KSEL * 64; e += 256) {
            int k = e >> 6, q4 = e & 63;
            float4 v = make_float4(0.f, 0.f, 0.f, 0.f);
            if (k < kept) v = Pn4[(size_t)(b * Tn + sIdx[k]) * 64 + q4];
            *(float4*)&sM[k][q4 << 2] = v;
        }
    }
    // normalize I row into sM[15]
    float iv = g_I[(size_t)(b * Tn + t) * 1024 + r * 256 + tid];
    float ss = iv * iv;
#pragma unroll
    for (int o = 16; o; o >>= 1) ss += __shfl_xor_sync(0xffffffffu, ss, o);
    if (lane == 0) sred[wid] = ss;
    __syncthreads();
    float tot = 0.f;
#pragma unroll
    for (int w = 0; w < 8; w++) tot += sred[w];
    float inv = 1.f / fmaxf(sqrtf(tot), 1e-12f);
    sM[15][tid] = iv * inv;
    __syncthreads();

    // ---- gram: warp w computes rows 2w, 2w+1 of S = M M^T (16x16) ----
    {
        int k0 = 2 * wid, k1 = 2 * wid + 1;
        float p0[16], p1[16];
#pragma unroll
        for (int j = 0; j < 16; j++) { p0[j] = 0.f; p1[j] = 0.f; }
#pragma unroll
        for (int q = 0; q < 8; q++) {
            int d = q * 32 + lane;
            float m[16];
#pragma unroll
            for (int i = 0; i < 16; i++) m[i] = sM[i][d];
            float a0 = m[k0 & 15];
            float a1 = m[k1 & 15];
#pragma unroll
            for (int j = 0; j < 16; j++) {
                p0[j] += a0 * m[j];
                p1[j] += a1 * m[j];
            }
        }
#pragma unroll
        for (int j = 0; j < 16; j++) {
            float s0 = p0[j], s1 = p1[j];
#pragma unroll
            for (int o = 16; o; o >>= 1) {
                s0 += __shfl_xor_sync(0xffffffffu, s0, o);
                s1 += __shfl_xor_sync(0xffffffffu, s1, o);
            }
            if (lane == j) { sS[k0][j] = s0; sS[k1][j] = s1; }
        }
    }
    __syncthreads();

    // build rel features (15 x 17)
    if (tid < KSEL * 17) {
        int k = tid / 17, i = tid - k * 17;
        float v;
        if (i < 15)       v = fminf(fmaxf(sS[k][i], -1.f), 1.f);
        else if (i == 15) v = fminf(fmaxf(sS[15][k], -1.f), 1.f);
        else              v = (k < kept) ? (float)(t - sIdx[k]) * (1.f / 2048.f) : 0.f;
        sRel[k][i] = v;
    }
    __syncthreads();

    // layer1: 17 -> 64 + swish(pi/sqrt3)  (W1 via LDG/L1 - only 4.3KB)
    for (int task = tid; task < KSEL * 64; task += 256) {
        int k = task >> 6, j = task & 63;
        float acc = b1[j];
#pragma unroll
        for (int i = 0; i < 17; i++) acc += sRel[k][i] * W1[i * 64 + j];
        sH1[k][j] = acc / (1.f + expf(-SCALE_ACT * acc));
    }
    __syncthreads();

    // layer2: 64 -> 64 from smem weights
    {
        int j = tid & 63, kq = tid >> 6;
        float acc[4];
        float bj = sb2[j];
#pragma unroll
        for (int i = 0; i < 4; i++) acc[i] = bj;
#pragma unroll 8
        for (int ii = 0; ii < 64; ii++) {
            float w = sW2[ii * 64 + j];
#pragma unroll
            for (int i = 0; i < 4; i++) {
                int k = kq + 4 * i;
                float h = (k < KSEL) ? sH1[k][ii] : 0.f;
                acc[i] += h * w;
            }
        }
#pragma unroll
        for (int i = 0; i < 4; i++) {
            int k = kq + 4 * i;
            if (k < KSEL) sH2[k][j] = acc[i];
        }
    }
    __syncthreads();

    // heads v3: 45 dot-64 tasks spread over 8 warps, shfl-tree reduce
    for (int task = wid; task < 45; task += 8) {
        int k = task / 3, c = task - (task / 3) * 3;
        float wa = (c == 0) ? sWc[lane * 2] : (c == 1) ? sWc[lane * 2 + 1] : sWm[lane];
        float wb = (c == 0) ? sWc[(lane + 32) * 2] : (c == 1) ? sWc[(lane + 32) * 2 + 1]
                                                             : sWm[lane + 32];
        float s = sH2[k][lane] * wa + sH2[k][lane + 32] * wb;
#pragma unroll
        for (int o = 16; o; o >>= 1) s += __shfl_xor_sync(0xffffffffu, s, o);
        if (lane == 0) {
            float acc = ((c == 2) ? sbm1[0] : sbc2[c]) + s;
            if (c < 2) sZ[k][c] = tanhf(acc); else sMix[k] = acc;
        }
    }
    __syncthreads();

    // softmax over kept + grid coords
    if (tid < 32) {
        float m = (tid < kept) ? sMix[tid] : -INFINITY;
        float mx = m;
#pragma unroll
        for (int o = 16; o; o >>= 1) mx = fmaxf(mx, __shfl_xor_sync(0xffffffffu, mx, o));
        float e = (tid < kept) ? expf(m - mx) : 0.f;
        float se = e;
#pragma unroll
        for (int o = 16; o; o >>= 1) se += __shfl_xor_sync(0xffffffffu, se, o);
        if (tid < KSEL) {
            sWk[tid] = e / se;
            float gx = fminf(fmaxf((sZ[tid][0] + 1.f) * 7.5f, 0.f), 15.f);
            float gy = fminf(fmaxf((sZ[tid][1] + 1.f) * 7.5f, 0.f), 15.f);
            float x0f = floorf(gx), y0f = floorf(gy);
            sX0[tid] = (int)x0f; sY0[tid] = (int)y0f;
            sWx[tid] = gx - x0f; sWy[tid] = gy - y0f;
        }
    }
    __syncthreads();

    // bilinear sample + weighted sum: 64 threads x float4 (coalesced)
    if (tid < 64) {
        const float4* P4 = (const float4*)g_palT;
        float4 acc = make_float4(0.f, 0.f, 0.f, 0.f);
        for (int k = 0; k < kept; k++) {
            float wk = sWk[k];
            int x0 = sX0[k], y0 = sY0[k];
            int x1 = min(x0 + 1, 15), y1 = min(y0 + 1, 15);
            float wx = sWx[k], wy = sWy[k];
            float w00 = wk * (1.f - wx) * (1.f - wy);
            float w01 = wk * wx * (1.f - wy);
            float w10 = wk * (1.f - wx) * wy;
            float w11 = wk * wx * wy;
            float4 v00 = P4[(y0 * 16 + x0) * 64 + tid];
            float4 v01 = P4[(y0 * 16 + x1) * 64 + tid];
            float4 v10 = P4[(y1 * 16 + x0) * 64 + tid];
            float4 v11 = P4[(y1 * 16 + x1) * 64 + tid];
            acc.x += w00 * v00.x + w01 * v01.x + w10 * v10.x + w11 * v11.x;
            acc.y += w00 * v00.y + w01 * v01.y + w10 * v10.y + w11 * v11.y;
            acc.z += w00 * v00.z + w01 * v01.z + w10 * v10.z + w11 * v11.z;
            acc.w += w00 * v00.w + w01 * v01.w + w10 * v10.w + w11 * v11.w;
        }
        float4* Vout = (float4*)&g_V[(size_t)(b * Tn + t) * 1024 + r * 256];
        Vout[tid] = acc;
    }
}

// ---------------- host launcher ----------------
extern "C" void kernel_launch(void* const* d_in, const int* in_sizes, int n_in,
                              void* d_out, int out_size) {
    const float* x       = (const float*)d_in[0];
    const float* Wi      = (const float*)d_in[1];
    const float* Wp      = (const float*)d_in[2];
    const float* W1      = (const float*)d_in[3];
    const float* b1      = (const float*)d_in[4];
    const float* W2      = (const float*)d_in[5];
    const float* b2      = (const float*)d_in[6];
    const float* Wc      = (const float*)d_in[7];
    const float* bc      = (const float*)d_in[8];
    const float* Wm      = (const float*)d_in[9];
    const float* bm      = (const float*)d_in[10];
    const float* palette = (const float*)d_in[11];
    const float* Wo      = (const float*)d_in[12];
    float* out = (float*)d_out;

    float *pI, *pP, *pV;
    cudaGetSymbolAddress((void**)&pI, g_I);
    cudaGetSymbolAddress((void**)&pP, g_P);
    cudaGetSymbolAddress((void**)&pV, g_V);

    k_inv<<<1, 128>>>();
    k_rope_tables<<<Tn, 128>>>();
    k_palT<<<Dm, 256>>>(palette);

    // I = x @ Wi  (4096 x 1024, K=256)
    k_gemm128<<<dim3(8, 32), 256>>>(x, Wi, pI, 256, 256, 1024, 1024, 1.0f);
    // P = x @ Wp  (4096 x 256, K=256) -- SELECTION-CRITICAL: sequential-k,
    // bit-identical to the R9/R12 passing runs. NO split-K here.
    k_gemm_rr<<<dim3(4, 64), 256>>>(x, Wp, pP, 256, 256, 256, 256, 1.0f);

    k_rope_I<<<(Bqn * Tn * BRn * 128) / 256, 256>>>();
    k_rope_P<<<Bqn * Tn, 128>>>();

    k_logits128<<<dim3(16, 16, Bqn * BRn), 256>>>();
    k_topk<<<Bqn * BRn * Tn, 256>>>();
    k_constellation<<<Bqn * BRn * Tn, 256>>>(W1, b1, W2, b2, Wc, bc, Wm, bm);

    // y = 0.25 * V(4096x1024) @ Wo(1024x256) split-K x4 (post-selection, safe)
    k_gemm128sk<<<dim3(2, 32, 4), 256>>>(pV, Wo, 256, 1024, 256, 256);
    k_sumK<<<1024, 256>>>(out, 0.25f, 4096 * 256 / 4);
}